// round 6
// baseline (speedup 1.0000x reference)
#include <cuda_runtime.h>
#include <math.h>

#define N_NODES 50000
#define E_EDGES 800000
#define G_GRAPHS 512
#define HID 64
#define DOUT 128
#define LAYERS 3
#define NEG_SLOPE 0.2f
#define BN_EPS 1e-5f

// ---------------- scratch (device globals; no allocation allowed) ----------------
__device__ float g_h  [N_NODES * HID];
__device__ float g_xl [N_NODES * HID];
__device__ float g_xr [N_NODES * HID];
__device__ int   g_hist[N_NODES];
__device__ int   g_off [N_NODES + 1];
__device__ int   g_cursor[N_NODES];
__device__ int   g_srcS[E_EDGES];
__device__ float g_eaS [E_EDGES * 16];
__device__ float g_cnt [G_GRAPHS];

// ---------------- embedding GEMM (also zeroes histogram for CSR build) ----------
__global__ void gemm_emb(const float* __restrict__ A, const float* __restrict__ W,
                         const float* __restrict__ bias) {
    __shared__ float Ws[64][68];
    __shared__ float As[64][68];
    int t = threadIdx.x;           // 256 threads
    int row0 = blockIdx.x * 64;

    int gid = blockIdx.x * 256 + t;
    if (gid < N_NODES) g_hist[gid] = 0;   // piggyback: zero histogram

    #pragma unroll
    for (int i = t; i < 4096; i += 256) { int c = i >> 6, k = i & 63; Ws[c][k] = W[i]; }
    #pragma unroll
    for (int i = t; i < 4096; i += 256) {
        int r = i >> 6, k = i & 63; int gr = row0 + r;
        As[r][k] = (gr < N_NODES) ? A[gr * 64 + k] : 0.f;
    }
    __syncthreads();

    int c  = t & 63;
    int rb = t >> 6;
    float acc[16];
    #pragma unroll
    for (int r = 0; r < 16; r++) acc[r] = 0.f;

    #pragma unroll
    for (int k4 = 0; k4 < 16; k4++) {
        float4 w4 = *(const float4*)&Ws[c][k4 * 4];
        #pragma unroll
        for (int r = 0; r < 16; r++) {
            float4 a4 = *(const float4*)&As[rb * 16 + r][k4 * 4];
            acc[r] += w4.x * a4.x + w4.y * a4.y + w4.z * a4.z + w4.w * a4.w;
        }
    }
    float bb = bias[c];
    #pragma unroll
    for (int r = 0; r < 16; r++) {
        int gr = row0 + rb * 16 + r;
        if (gr < N_NODES) g_h[gr * 64 + c] = acc[r] + bb;
    }
}

// ---------------- CSR build ----------------
__global__ void hist_count(const int* __restrict__ ei) {
    int e = blockIdx.x * blockDim.x + threadIdx.x;
    if (e < E_EDGES) atomicAdd(&g_hist[ei[E_EDGES + e]], 1);
}

__global__ void scan_hist() {      // single block, 1024 threads
    __shared__ int sp[1024];
    const int CH = 49;             // 1024*49 = 50176 >= 50000
    int t = threadIdx.x;
    int base = t * CH;
    int sum = 0;
    for (int i = 0; i < CH; i++) {
        int idx = base + i;
        if (idx < N_NODES) sum += g_hist[idx];
    }
    sp[t] = sum;
    __syncthreads();
    for (int off = 1; off < 1024; off <<= 1) {
        int v = (t >= off) ? sp[t - off] : 0;
        __syncthreads();
        sp[t] += v;
        __syncthreads();
    }
    int run = (t == 0) ? 0 : sp[t - 1];
    for (int i = 0; i < CH; i++) {
        int idx = base + i;
        if (idx < N_NODES) {
            g_off[idx] = run;
            g_cursor[idx] = run;
            run += g_hist[idx];
        }
    }
    if (t == 1023) g_off[N_NODES] = sp[1023];
}

__global__ void scatter_edges(const int* __restrict__ ei, const float* __restrict__ eattr) {
    int e = blockIdx.x * blockDim.x + threadIdx.x;
    if (e >= E_EDGES) return;
    int src = ei[e];
    int dst = ei[E_EDGES + e];
    int pos = atomicAdd(&g_cursor[dst], 1);
    g_srcS[pos] = src;
    const float4* s4 = (const float4*)(eattr + (size_t)e * 16);
    float4* d4 = (float4*)(g_eaS + (size_t)pos * 16);
    d4[0] = s4[0]; d4[1] = s4[1]; d4[2] = s4[2]; d4[3] = s4[3];
}

// ---------------- fused xl/xr GEMM (transposed W in smem: conflict-free) --------
__global__ void gemm_xlxr(const float* __restrict__ Wl, const float* __restrict__ bl,
                          const float* __restrict__ Wr, const float* __restrict__ br) {
    __shared__ float sWlT[64][64];   // [k][c]
    __shared__ float sWrT[64][64];
    __shared__ float sA[32][64];
    int t = threadIdx.x;             // 256
    int row0 = blockIdx.x * 32;

    #pragma unroll
    for (int i = t; i < 4096; i += 256) {
        int c = i >> 6, k = i & 63;
        sWlT[k][c] = Wl[i];
        sWrT[k][c] = Wr[i];
    }
    #pragma unroll
    for (int i = t; i < 2048; i += 256) {
        int r = i >> 6, k = i & 63; int gr = row0 + r;
        sA[r][k] = (gr < N_NODES) ? g_h[gr * 64 + k] : 0.f;
    }
    __syncthreads();

    int c  = t & 63;
    int rb = t >> 6;                 // 0..3, rows rb*8 .. rb*8+7
    float accL[8], accR[8];
    #pragma unroll
    for (int r = 0; r < 8; r++) { accL[r] = 0.f; accR[r] = 0.f; }

    #pragma unroll
    for (int k4 = 0; k4 < 16; k4++) {
        float wl_[4], wr_[4];
        #pragma unroll
        for (int q = 0; q < 4; q++) { wl_[q] = sWlT[k4 * 4 + q][c]; wr_[q] = sWrT[k4 * 4 + q][c]; }
        #pragma unroll
        for (int r = 0; r < 8; r++) {
            float4 a = *(const float4*)&sA[rb * 8 + r][k4 * 4];
            accL[r] += wl_[0] * a.x + wl_[1] * a.y + wl_[2] * a.z + wl_[3] * a.w;
            accR[r] += wr_[0] * a.x + wr_[1] * a.y + wr_[2] * a.z + wr_[3] * a.w;
        }
    }
    float bll = bl[c], brr = br[c];
    #pragma unroll
    for (int r = 0; r < 8; r++) {
        int gr = row0 + rb * 8 + r;
        if (gr < N_NODES) {
            g_xl[gr * 64 + c] = accL[r] + bll;
            g_xr[gr * 64 + c] = accR[r] + brr;
        }
    }
}

// ---- fused GAT layer: warp/node, half-warp/edge, 2-stage software pipeline ----
__global__ void __launch_bounds__(256, 3)
gat_layer(const float* __restrict__ We, const float* __restrict__ att,
          const float* __restrict__ cb, const float* __restrict__ gamma,
          const float* __restrict__ beta, const float* __restrict__ mean,
          const float* __restrict__ var) {
    __shared__ float4 sWe[16][16];   // sWe[k][cg] = We rows cg*4..cg*4+3 at col k
    int t = threadIdx.x;             // 256 threads = 8 warps = 8 nodes
    {
        int k = t >> 4, cg = t & 15;
        sWe[k][cg] = make_float4(We[(cg * 4 + 0) * 16 + k], We[(cg * 4 + 1) * 16 + k],
                                 We[(cg * 4 + 2) * 16 + k], We[(cg * 4 + 3) * 16 + k]);
    }
    __syncthreads();

    int nid = (blockIdx.x * blockDim.x + t) >> 5;   // grid exact: 6250*8 = 50000
    int lane = t & 31;
    int half = lane >> 4;            // 0 or 1: which edge of the pair
    int cg   = lane & 15;            // channel group: channels cg*4 .. cg*4+3

    float4 vr = *(const float4*)&g_xr[nid * 64 + cg * 4];
    float4 a4 = __ldg((const float4*)att + cg);

    int jb = g_off[nid], je = g_off[nid + 1];

    float4 acc = make_float4(0.f, 0.f, 0.f, 0.f);
    float accd = 0.f;

    // ---- pipeline prologue: load edge jb+half fully, and src of jb+2+half ----
    int j0p = jb + half;
    int jc0 = min(j0p, E_EDGES - 1);
    int s0  = __ldg(&g_srcS[jc0]);
    float4 vl = *(const float4*)&g_xl[s0 * 64 + cg * 4];
    const float4* eap = (const float4*)(g_eaS + (size_t)jc0 * 16);
    float4 e0 = eap[0], e1 = eap[1], e2 = eap[2], e3 = eap[3];
    int s_nxt = __ldg(&g_srcS[min(j0p + 2, E_EDGES - 1)]);

    for (int j0 = jb; j0 < je; j0 += 2) {
        // ---- prefetch for iteration j0+2 (data) and j0+4 (src index) ----
        int jp  = min(j0 + 2 + half, E_EDGES - 1);
        float4 vl_n = *(const float4*)&g_xl[s_nxt * 64 + cg * 4];
        const float4* ean = (const float4*)(g_eaS + (size_t)jp * 16);
        float4 f0 = ean[0], f1 = ean[1], f2 = ean[2], f3 = ean[3];
        int s_nn = __ldg(&g_srcS[min(j0 + 4 + half, E_EDGES - 1)]);

        // ---- compute current edge ----
        bool valid = (j0 + half) < je;
        float m0 = vl.x + vr.x, m1 = vl.y + vr.y, m2 = vl.z + vr.z, m3 = vl.w + vr.w;
        #pragma unroll
        for (int q = 0; q < 4; q++) {
            float4 eq = (q == 0) ? e0 : (q == 1) ? e1 : (q == 2) ? e2 : e3;
            float ev0 = eq.x, ev1 = eq.y, ev2 = eq.z, ev3 = eq.w;
            float4 w0 = sWe[q * 4 + 0][cg];
            float4 w1 = sWe[q * 4 + 1][cg];
            float4 w2 = sWe[q * 4 + 2][cg];
            float4 w3 = sWe[q * 4 + 3][cg];
            m0 = fmaf(w0.x, ev0, m0); m1 = fmaf(w0.y, ev0, m1);
            m2 = fmaf(w0.z, ev0, m2); m3 = fmaf(w0.w, ev0, m3);
            m0 = fmaf(w1.x, ev1, m0); m1 = fmaf(w1.y, ev1, m1);
            m2 = fmaf(w1.z, ev1, m2); m3 = fmaf(w1.w, ev1, m3);
            m0 = fmaf(w2.x, ev2, m0); m1 = fmaf(w2.y, ev2, m1);
            m2 = fmaf(w2.z, ev2, m2); m3 = fmaf(w2.w, ev2, m3);
            m0 = fmaf(w3.x, ev3, m0); m1 = fmaf(w3.y, ev3, m1);
            m2 = fmaf(w3.z, ev3, m2); m3 = fmaf(w3.w, ev3, m3);
        }
        m0 = fmaxf(m0, NEG_SLOPE * m0);
        m1 = fmaxf(m1, NEG_SLOPE * m1);
        m2 = fmaxf(m2, NEG_SLOPE * m2);
        m3 = fmaxf(m3, NEG_SLOPE * m3);

        float p = m0 * a4.x + m1 * a4.y + m2 * a4.z + m3 * a4.w;
        #pragma unroll
        for (int o = 1; o <= 8; o <<= 1) p += __shfl_xor_sync(0xffffffffu, p, o);

        float w = valid ? __expf(p) : 0.f;   // logits small; stable without segment-max
        accd += w;
        acc.x = fmaf(w, vl.x, acc.x);
        acc.y = fmaf(w, vl.y, acc.y);
        acc.z = fmaf(w, vl.z, acc.z);
        acc.w = fmaf(w, vl.w, acc.w);

        // ---- rotate pipeline ----
        vl = vl_n; e0 = f0; e1 = f1; e2 = f2; e3 = f3; s_nxt = s_nn;
    }

    // merge the two half-warp accumulators
    acc.x += __shfl_xor_sync(0xffffffffu, acc.x, 16);
    acc.y += __shfl_xor_sync(0xffffffffu, acc.y, 16);
    acc.z += __shfl_xor_sync(0xffffffffu, acc.z, 16);
    acc.w += __shfl_xor_sync(0xffffffffu, acc.w, 16);
    accd  += __shfl_xor_sync(0xffffffffu, accd, 16);

    if (half == 0) {
        float inv = 1.f / (accd + 1e-16f);
        float4 b4  = __ldg((const float4*)cb + cg);
        float4 mu4 = __ldg((const float4*)mean + cg);
        float4 v4  = __ldg((const float4*)var + cg);
        float4 gm4 = __ldg((const float4*)gamma + cg);
        float4 bt4 = __ldg((const float4*)beta + cg);
        float o[4] = {acc.x * inv + b4.x, acc.y * inv + b4.y,
                      acc.z * inv + b4.z, acc.w * inv + b4.w};
        float mu[4] = {mu4.x, mu4.y, mu4.z, mu4.w};
        float vv[4] = {v4.x, v4.y, v4.z, v4.w};
        float gm[4] = {gm4.x, gm4.y, gm4.z, gm4.w};
        float bt[4] = {bt4.x, bt4.y, bt4.z, bt4.w};
        #pragma unroll
        for (int q = 0; q < 4; q++) {
            float z = (o[q] - mu[q]) * rsqrtf(vv[q] + BN_EPS) * gm[q] + bt[q];
            o[q] = 0.5f * z * (1.f + erff(z * 0.70710678118654752f));
        }
        float4 h = *(float4*)&g_h[nid * 64 + cg * 4];
        h.x += o[0]; h.y += o[1]; h.z += o[2]; h.w += o[3];
        *(float4*)&g_h[nid * 64 + cg * 4] = h;
    }
}

// ---------------- pooling ----------------
__global__ void init_pool(float* __restrict__ out) {
    int idx = blockIdx.x * blockDim.x + threadIdx.x;
    if (idx < G_GRAPHS * DOUT) out[idx] = 0.f;
    if (idx < G_GRAPHS) g_cnt[idx] = 0.f;
}

__global__ void count_nodes(const int* __restrict__ batch) {
    int n = blockIdx.x * blockDim.x + threadIdx.x;
    if (n < N_NODES) atomicAdd(&g_cnt[batch[n]], 1.f);
}

__global__ void lin_pool(const float* __restrict__ W, const float* __restrict__ bias,
                         const int* __restrict__ batch, float* __restrict__ pooled) {
    __shared__ float Ws[128][68];
    __shared__ float As[32][68];
    int t = threadIdx.x;            // 256
    int row0 = blockIdx.x * 32;

    for (int i = t; i < 128 * 64; i += 256) { int c = i >> 6, k = i & 63; Ws[c][k] = W[i]; }
    for (int i = t; i < 32 * 64; i += 256) {
        int r = i >> 6, k = i & 63; int gr = row0 + r;
        As[r][k] = (gr < N_NODES) ? g_h[gr * 64 + k] : 0.f;
    }
    __syncthreads();

    int c  = t & 127;
    int rb = t >> 7;
    float acc[16];
    #pragma unroll
    for (int r = 0; r < 16; r++) acc[r] = 0.f;

    #pragma unroll
    for (int k4 = 0; k4 < 16; k4++) {
        float4 w4 = *(const float4*)&Ws[c][k4 * 4];
        #pragma unroll
        for (int r = 0; r < 16; r++) {
            float4 a4 = *(const float4*)&As[rb * 16 + r][k4 * 4];
            acc[r] += w4.x * a4.x + w4.y * a4.y + w4.z * a4.z + w4.w * a4.w;
        }
    }
    float bb = bias[c];
    #pragma unroll
    for (int r = 0; r < 16; r++) {
        int gr = row0 + rb * 16 + r;
        if (gr < N_NODES)
            atomicAdd(&pooled[batch[gr] * DOUT + c], acc[r] + bb);
    }
}

__global__ void finalize(float* __restrict__ out) {
    int idx = blockIdx.x * blockDim.x + threadIdx.x;
    if (idx >= G_GRAPHS * DOUT) return;
    out[idx] /= fmaxf(g_cnt[idx >> 7], 1.f);
}

// ---------------- launch ----------------
extern "C" void kernel_launch(void* const* d_in, const int* in_sizes, int n_in,
                              void* d_out, int out_size) {
    const float* x         = (const float*)d_in[0];
    const int*   ei        = (const int*)  d_in[1];
    const float* eattr     = (const float*)d_in[2];
    const int*   batch     = (const int*)  d_in[3];
    const float* emb_W     = (const float*)d_in[4];
    const float* emb_b     = (const float*)d_in[5];
    const float* Wl        = (const float*)d_in[6];
    const float* bl        = (const float*)d_in[7];
    const float* Wr        = (const float*)d_in[8];
    const float* br        = (const float*)d_in[9];
    const float* We        = (const float*)d_in[10];
    const float* att       = (const float*)d_in[11];
    const float* conv_bias = (const float*)d_in[12];
    const float* gamma     = (const float*)d_in[13];
    const float* beta      = (const float*)d_in[14];
    const float* mean      = (const float*)d_in[15];
    const float* var       = (const float*)d_in[16];
    const float* lin_W     = (const float*)d_in[17];
    const float* lin_b     = (const float*)d_in[18];
    float* out = (float*)d_out;

    const int EMB_BLOCKS  = (N_NODES + 63) / 64;            // 782
    const int XLR_BLOCKS  = (N_NODES + 31) / 32;            // 1563
    const int EDGE_BLOCKS = (E_EDGES + 255) / 256;          // 3125
    const int GAT_BLOCKS  = N_NODES / 8;                    // 6250 (8 nodes/block, exact)

    gemm_emb<<<EMB_BLOCKS, 256>>>(x, emb_W, emb_b);
    hist_count<<<EDGE_BLOCKS, 256>>>(ei);
    scan_hist<<<1, 1024>>>();
    scatter_edges<<<EDGE_BLOCKS, 256>>>(ei, eattr);

    for (int l = 0; l < LAYERS; l++) {
        gemm_xlxr<<<XLR_BLOCKS, 256>>>(Wl + l * 4096, bl + l * 64, Wr + l * 4096, br + l * 64);
        gat_layer<<<GAT_BLOCKS, 256>>>(We + l * 1024, att + l * 64, conv_bias + l * 64,
                                       gamma + l * 64, beta + l * 64, mean + l * 64, var + l * 64);
    }

    init_pool<<<(G_GRAPHS * DOUT + 255) / 256, 256>>>(out);
    count_nodes<<<(N_NODES + 255) / 256, 256>>>(batch);
    lin_pool<<<(N_NODES + 31) / 32, 256>>>(lin_W, lin_b, batch, out);
    finalize<<<(G_GRAPHS * DOUT + 255) / 256, 256>>>(out);
}

// round 7
// speedup vs baseline: 1.0515x; 1.0515x over previous
#include <cuda_runtime.h>
#include <math.h>

#define N_NODES 50000
#define E_EDGES 800000
#define G_GRAPHS 512
#define HID 64
#define DOUT 128
#define LAYERS 3
#define NEG_SLOPE 0.2f
#define BN_EPS 1e-5f

typedef unsigned long long ull;

// ---------------- scratch (device globals; no allocation allowed) ----------------
__device__ float g_h  [N_NODES * HID];
__device__ float g_xl [N_NODES * HID];
__device__ float g_xr [N_NODES * HID];
__device__ int   g_hist[N_NODES];
__device__ int   g_off [N_NODES + 1];
__device__ int   g_cursor[N_NODES];
__device__ int   g_srcS[E_EDGES];
__device__ float g_eaS [E_EDGES * 16];
__device__ float g_cnt [G_GRAPHS];
__device__ int   g_flag;
__device__ int   g_done;

// ---------------- packed fp32x2 helpers (sm_103a FFMA2 — PTX only) ----------------
__device__ __forceinline__ ull pk(float x, float y) {
    ull r; asm("mov.b64 %0, {%1, %2};" : "=l"(r) : "f"(x), "f"(y)); return r;
}
__device__ __forceinline__ void upk(ull v, float& x, float& y) {
    asm("mov.b64 {%0, %1}, %2;" : "=f"(x), "=f"(y) : "l"(v));
}
__device__ __forceinline__ ull fma2(ull a, ull b, ull c) {
    ull d; asm("fma.rn.f32x2 %0, %1, %2, %3;" : "=l"(d) : "l"(a), "l"(b), "l"(c)); return d;
}
__device__ __forceinline__ ull add2(ull a, ull b) {
    ull d; asm("add.rn.f32x2 %0, %1, %2;" : "=l"(d) : "l"(a), "l"(b)); return d;
}

// ------- launch 1: embedding GEMM (blocks 0..781) + edge histogram (blocks 782+) -------
__global__ void emb_hist(const float* __restrict__ A, const float* __restrict__ W,
                         const float* __restrict__ bias, const int* __restrict__ ei) {
    int t = threadIdx.x;
    if (blockIdx.x >= 782) {
        int e = (blockIdx.x - 782) * 256 + t;
        if (e < E_EDGES) atomicAdd(&g_hist[ei[E_EDGES + e]], 1);
        return;
    }
    __shared__ float Ws[64][68];
    __shared__ float As[64][68];
    int row0 = blockIdx.x * 64;

    #pragma unroll
    for (int i = t; i < 4096; i += 256) { int c = i >> 6, k = i & 63; Ws[c][k] = W[i]; }
    #pragma unroll
    for (int i = t; i < 4096; i += 256) {
        int r = i >> 6, k = i & 63; int gr = row0 + r;
        As[r][k] = (gr < N_NODES) ? A[gr * 64 + k] : 0.f;
    }
    __syncthreads();

    int c  = t & 63;
    int rb = t >> 6;
    float acc[16];
    #pragma unroll
    for (int r = 0; r < 16; r++) acc[r] = 0.f;

    #pragma unroll
    for (int k4 = 0; k4 < 16; k4++) {
        float4 w4 = *(const float4*)&Ws[c][k4 * 4];
        #pragma unroll
        for (int r = 0; r < 16; r++) {
            float4 a4 = *(const float4*)&As[rb * 16 + r][k4 * 4];
            acc[r] += w4.x * a4.x + w4.y * a4.y + w4.z * a4.z + w4.w * a4.w;
        }
    }
    float bb = bias[c];
    #pragma unroll
    for (int r = 0; r < 16; r++) {
        int gr = row0 + rb * 16 + r;
        if (gr < N_NODES) g_h[gr * 64 + c] = acc[r] + bb;
    }
}

// ------- launch 2: block 0 scans hist -> offsets (and re-zeroes hist); others scatter ----
#define SCAT_BLOCKS 782           // ceil(800000/1024)
__global__ void scan_scatter(const int* __restrict__ ei, const float* __restrict__ eattr) {
    int t = threadIdx.x;           // 1024 threads
    if (blockIdx.x == 0) {
        __shared__ int sp[1024];
        const int CH = 49;         // 1024*49 = 50176 >= 50000
        int base = t * CH;
        int sum = 0;
        for (int i = 0; i < CH; i++) {
            int idx = base + i;
            if (idx < N_NODES) sum += g_hist[idx];
        }
        sp[t] = sum;
        __syncthreads();
        for (int off = 1; off < 1024; off <<= 1) {
            int v = (t >= off) ? sp[t - off] : 0;
            __syncthreads();
            sp[t] += v;
            __syncthreads();
        }
        int run = (t == 0) ? 0 : sp[t - 1];
        for (int i = 0; i < CH; i++) {
            int idx = base + i;
            if (idx < N_NODES) {
                g_off[idx] = run;
                g_cursor[idx] = run;
                run += g_hist[idx];
                g_hist[idx] = 0;          // reset for next graph replay
            }
        }
        if (t == 1023) g_off[N_NODES] = sp[1023];
        __threadfence();
        __syncthreads();
        if (t == 0) atomicExch(&g_flag, 1);
        return;
    }

    // scatter blocks: wait for offsets
    if (t == 0) { while (atomicAdd(&g_flag, 0) == 0) {} }
    __syncthreads();
    __threadfence();

    int e = (blockIdx.x - 1) * 1024 + t;
    if (e < E_EDGES) {
        int src = ei[e];
        int dst = ei[E_EDGES + e];
        int pos = atomicAdd(&g_cursor[dst], 1);
        g_srcS[pos] = src;
        const float4* s4 = (const float4*)(eattr + (size_t)e * 16);
        float4* d4 = (float4*)(g_eaS + (size_t)pos * 16);
        d4[0] = s4[0]; d4[1] = s4[1]; d4[2] = s4[2]; d4[3] = s4[3];
    }
    __syncthreads();
    if (t == 0) {
        int d = atomicAdd(&g_done, 1);
        if (d == SCAT_BLOCKS - 1) {        // last scatter block resets flags
            g_done = 0;
            atomicExch(&g_flag, 0);
        }
    }
}

// ---------------- fused xl/xr GEMM (padded transposed W: conflict-free) --------
__global__ void gemm_xlxr(const float* __restrict__ Wl, const float* __restrict__ bl,
                          const float* __restrict__ Wr, const float* __restrict__ br) {
    __shared__ float sWlT[64][65];   // [k][c], pad 65 so transpose write is conflict-free
    __shared__ float sWrT[64][65];
    __shared__ float sA[32][64];
    int t = threadIdx.x;             // 256
    int row0 = blockIdx.x * 32;

    #pragma unroll
    for (int i = t; i < 4096; i += 256) {
        int c = i >> 6, k = i & 63;
        sWlT[k][c] = Wl[i];
        sWrT[k][c] = Wr[i];
    }
    #pragma unroll
    for (int i = t; i < 2048; i += 256) {
        int r = i >> 6, k = i & 63; int gr = row0 + r;
        sA[r][k] = (gr < N_NODES) ? g_h[gr * 64 + k] : 0.f;
    }
    __syncthreads();

    int c  = t & 63;
    int rb = t >> 6;                 // 0..3, rows rb*8 .. rb*8+7
    float accL[8], accR[8];
    #pragma unroll
    for (int r = 0; r < 8; r++) { accL[r] = 0.f; accR[r] = 0.f; }

    #pragma unroll
    for (int k4 = 0; k4 < 16; k4++) {
        float wl_[4], wr_[4];
        #pragma unroll
        for (int q = 0; q < 4; q++) { wl_[q] = sWlT[k4 * 4 + q][c]; wr_[q] = sWrT[k4 * 4 + q][c]; }
        #pragma unroll
        for (int r = 0; r < 8; r++) {
            float4 a = *(const float4*)&sA[rb * 8 + r][k4 * 4];
            accL[r] += wl_[0] * a.x + wl_[1] * a.y + wl_[2] * a.z + wl_[3] * a.w;
            accR[r] += wr_[0] * a.x + wr_[1] * a.y + wr_[2] * a.z + wr_[3] * a.w;
        }
    }
    float bll = bl[c], brr = br[c];
    #pragma unroll
    for (int r = 0; r < 8; r++) {
        int gr = row0 + rb * 8 + r;
        if (gr < N_NODES) {
            g_xl[gr * 64 + c] = accL[r] + bll;
            g_xr[gr * 64 + c] = accR[r] + brr;
        }
    }
}

// ---- fused GAT layer: warp/node, half-warp/edge, packed f32x2 FMA ----
__global__ void __launch_bounds__(256, 4)
gat_layer(const float* __restrict__ We, const float* __restrict__ att,
          const float* __restrict__ cb, const float* __restrict__ gamma,
          const float* __restrict__ beta, const float* __restrict__ mean,
          const float* __restrict__ var) {
    __shared__ float4 sWe[16][16];   // sWe[k][cg] = We rows cg*4..cg*4+3 at col k
    int t = threadIdx.x;             // 256 threads = 8 warps = 8 nodes
    {
        int k = t >> 4, cg = t & 15;
        sWe[k][cg] = make_float4(We[(cg * 4 + 0) * 16 + k], We[(cg * 4 + 1) * 16 + k],
                                 We[(cg * 4 + 2) * 16 + k], We[(cg * 4 + 3) * 16 + k]);
    }
    __syncthreads();

    int nid = (blockIdx.x * 256 + t) >> 5;   // grid exact: 6250*8 = 50000
    int lane = t & 31;
    int half = lane >> 4;            // 0 or 1: which edge of the pair
    int cg   = lane & 15;            // channel group: channels cg*4 .. cg*4+3

    float4 vr = *(const float4*)&g_xr[nid * 64 + cg * 4];
    ull vr01 = pk(vr.x, vr.y), vr23 = pk(vr.z, vr.w);
    float4 a4 = __ldg((const float4*)att + cg);

    int jb = g_off[nid], je = g_off[nid + 1];

    ull acc01 = 0ull, acc23 = 0ull;  // packed (0.f, 0.f)
    float accd = 0.f;

    for (int j0 = jb; j0 < je; j0 += 2) {
        int j = j0 + half;
        bool valid = (j < je);
        int jc = valid ? j : jb;                 // safe dummy index
        int s = __ldg(&g_srcS[jc]);
        float4 vl = *(const float4*)&g_xl[s * 64 + cg * 4];
        const float4* ea4 = (const float4*)(g_eaS + (size_t)jc * 16);
        float4 e0 = ea4[0], e1 = ea4[1], e2 = ea4[2], e3 = ea4[3];

        ull vl01 = pk(vl.x, vl.y), vl23 = pk(vl.z, vl.w);
        ull m01 = add2(vl01, vr01);
        ull m23 = add2(vl23, vr23);

        #define KSTEP(kk, av) { \
            ull aa = pk(av, av); \
            const ull* wp = (const ull*)&sWe[kk][cg]; \
            m01 = fma2(wp[0], aa, m01); \
            m23 = fma2(wp[1], aa, m23); }
        KSTEP(0,  e0.x) KSTEP(1,  e0.y) KSTEP(2,  e0.z) KSTEP(3,  e0.w)
        KSTEP(4,  e1.x) KSTEP(5,  e1.y) KSTEP(6,  e1.z) KSTEP(7,  e1.w)
        KSTEP(8,  e2.x) KSTEP(9,  e2.y) KSTEP(10, e2.z) KSTEP(11, e2.w)
        KSTEP(12, e3.x) KSTEP(13, e3.y) KSTEP(14, e3.z) KSTEP(15, e3.w)
        #undef KSTEP

        float m0, m1, m2, m3;
        upk(m01, m0, m1); upk(m23, m2, m3);
        m0 = fmaxf(m0, NEG_SLOPE * m0);
        m1 = fmaxf(m1, NEG_SLOPE * m1);
        m2 = fmaxf(m2, NEG_SLOPE * m2);
        m3 = fmaxf(m3, NEG_SLOPE * m3);

        float p = m0 * a4.x + m1 * a4.y + m2 * a4.z + m3 * a4.w;
        #pragma unroll
        for (int o = 1; o <= 8; o <<= 1) p += __shfl_xor_sync(0xffffffffu, p, o);

        float w = valid ? __expf(p) : 0.f;   // logits small; stable without segment-max
        accd += w;
        ull ww = pk(w, w);
        acc01 = fma2(ww, vl01, acc01);
        acc23 = fma2(ww, vl23, acc23);
    }

    float ax, ay, az, aw;
    upk(acc01, ax, ay); upk(acc23, az, aw);

    // merge the two half-warp accumulators
    ax += __shfl_xor_sync(0xffffffffu, ax, 16);
    ay += __shfl_xor_sync(0xffffffffu, ay, 16);
    az += __shfl_xor_sync(0xffffffffu, az, 16);
    aw += __shfl_xor_sync(0xffffffffu, aw, 16);
    accd += __shfl_xor_sync(0xffffffffu, accd, 16);

    if (half == 0) {
        float inv = 1.f / (accd + 1e-16f);
        float4 b4  = __ldg((const float4*)cb + cg);
        float4 mu4 = __ldg((const float4*)mean + cg);
        float4 v4  = __ldg((const float4*)var + cg);
        float4 gm4 = __ldg((const float4*)gamma + cg);
        float4 bt4 = __ldg((const float4*)beta + cg);
        float o[4] = {ax * inv + b4.x, ay * inv + b4.y,
                      az * inv + b4.z, aw * inv + b4.w};
        float mu[4] = {mu4.x, mu4.y, mu4.z, mu4.w};
        float vv[4] = {v4.x, v4.y, v4.z, v4.w};
        float gm[4] = {gm4.x, gm4.y, gm4.z, gm4.w};
        float bt[4] = {bt4.x, bt4.y, bt4.z, bt4.w};
        #pragma unroll
        for (int q = 0; q < 4; q++) {
            float z = (o[q] - mu[q]) * rsqrtf(vv[q] + BN_EPS) * gm[q] + bt[q];
            o[q] = 0.5f * z * (1.f + erff(z * 0.70710678118654752f));
        }
        float4 h = *(float4*)&g_h[nid * 64 + cg * 4];
        h.x += o[0]; h.y += o[1]; h.z += o[2]; h.w += o[3];
        *(float4*)&g_h[nid * 64 + cg * 4] = h;
    }
}

// ---------------- pooling ----------------
__global__ void init_pool(float* __restrict__ out) {
    int idx = blockIdx.x * blockDim.x + threadIdx.x;
    if (idx < G_GRAPHS * DOUT) out[idx] = 0.f;
    if (idx < G_GRAPHS) g_cnt[idx] = 0.f;
}

__global__ void count_nodes(const int* __restrict__ batch) {
    int n = blockIdx.x * blockDim.x + threadIdx.x;
    if (n < N_NODES) atomicAdd(&g_cnt[batch[n]], 1.f);
}

__global__ void lin_pool(const float* __restrict__ W, const float* __restrict__ bias,
                         const int* __restrict__ batch, float* __restrict__ pooled) {
    __shared__ float Ws[128][68];
    __shared__ float As[32][68];
    int t = threadIdx.x;            // 256
    int row0 = blockIdx.x * 32;

    for (int i = t; i < 128 * 64; i += 256) { int c = i >> 6, k = i & 63; Ws[c][k] = W[i]; }
    for (int i = t; i < 32 * 64; i += 256) {
        int r = i >> 6, k = i & 63; int gr = row0 + r;
        As[r][k] = (gr < N_NODES) ? g_h[gr * 64 + k] : 0.f;
    }
    __syncthreads();

    int c  = t & 127;
    int rb = t >> 7;
    float acc[16];
    #pragma unroll
    for (int r = 0; r < 16; r++) acc[r] = 0.f;

    #pragma unroll
    for (int k4 = 0; k4 < 16; k4++) {
        float4 w4 = *(const float4*)&Ws[c][k4 * 4];
        #pragma unroll
        for (int r = 0; r < 16; r++) {
            float4 a4 = *(const float4*)&As[rb * 16 + r][k4 * 4];
            acc[r] += w4.x * a4.x + w4.y * a4.y + w4.z * a4.z + w4.w * a4.w;
        }
    }
    float bb = bias[c];
    #pragma unroll
    for (int r = 0; r < 16; r++) {
        int gr = row0 + rb * 16 + r;
        if (gr < N_NODES)
            atomicAdd(&pooled[batch[gr] * DOUT + c], acc[r] + bb);
    }
}

__global__ void finalize(float* __restrict__ out) {
    int idx = blockIdx.x * blockDim.x + threadIdx.x;
    if (idx >= G_GRAPHS * DOUT) return;
    out[idx] /= fmaxf(g_cnt[idx >> 7], 1.f);
}

// ---------------- launch ----------------
extern "C" void kernel_launch(void* const* d_in, const int* in_sizes, int n_in,
                              void* d_out, int out_size) {
    const float* x         = (const float*)d_in[0];
    const int*   ei        = (const int*)  d_in[1];
    const float* eattr     = (const float*)d_in[2];
    const int*   batch     = (const int*)  d_in[3];
    const float* emb_W     = (const float*)d_in[4];
    const float* emb_b     = (const float*)d_in[5];
    const float* Wl        = (const float*)d_in[6];
    const float* bl        = (const float*)d_in[7];
    const float* Wr        = (const float*)d_in[8];
    const float* br        = (const float*)d_in[9];
    const float* We        = (const float*)d_in[10];
    const float* att       = (const float*)d_in[11];
    const float* conv_bias = (const float*)d_in[12];
    const float* gamma     = (const float*)d_in[13];
    const float* beta      = (const float*)d_in[14];
    const float* mean      = (const float*)d_in[15];
    const float* var       = (const float*)d_in[16];
    const float* lin_W     = (const float*)d_in[17];
    const float* lin_b     = (const float*)d_in[18];
    float* out = (float*)d_out;

    const int XLR_BLOCKS  = (N_NODES + 31) / 32;            // 1563
    const int GAT_BLOCKS  = N_NODES / 8;                    // 6250 (8 nodes/block, exact)

    // launch 1: embedding GEMM + edge histogram (merged)
    emb_hist<<<782 + 3125, 256>>>(x, emb_W, emb_b, ei);
    // launch 2: scan (block 0) + scatter (blocks 1..782) with flag handshake
    scan_scatter<<<1 + SCAT_BLOCKS, 1024>>>(ei, eattr);

    for (int l = 0; l < LAYERS; l++) {
        gemm_xlxr<<<XLR_BLOCKS, 256>>>(Wl + l * 4096, bl + l * 64, Wr + l * 4096, br + l * 64);
        gat_layer<<<GAT_BLOCKS, 256>>>(We + l * 1024, att + l * 64, conv_bias + l * 64,
                                       gamma + l * 64, beta + l * 64, mean + l * 64, var + l * 64);
    }

    init_pool<<<(G_GRAPHS * DOUT + 255) / 256, 256>>>(out);
    count_nodes<<<(N_NODES + 255) / 256, 256>>>(batch);
    lin_pool<<<(N_NODES + 31) / 32, 256>>>(lin_W, lin_b, batch, out);
    finalize<<<(G_GRAPHS * DOUT + 255) / 256, 256>>>(out);
}

// round 8
// speedup vs baseline: 1.2491x; 1.1879x over previous
#include <cuda_runtime.h>
#include <math.h>

#define N_NODES 50000
#define E_EDGES 800000
#define G_GRAPHS 512
#define HID 64
#define DOUT 128
#define LAYERS 3
#define NEG_SLOPE 0.2f
#define BN_EPS 1e-5f

typedef unsigned long long ull;

// ---------------- scratch (device globals; no allocation allowed) ----------------
__device__ float g_h  [N_NODES * HID];
__device__ float g_xl [N_NODES * HID];
__device__ float g_xr [N_NODES * HID];
__device__ int   g_hist[N_NODES];
__device__ int   g_off [N_NODES + 1];
__device__ int   g_cursor[N_NODES];
__device__ int   g_srcS[E_EDGES];
__device__ float g_eaS [E_EDGES * 16];
__device__ float g_cnt [G_GRAPHS];
__device__ int   g_flag;
__device__ int   g_done;

// ---------------- packed fp32x2 helpers (sm_103a FFMA2 — PTX only) ----------------
__device__ __forceinline__ ull pk(float x, float y) {
    ull r; asm("mov.b64 %0, {%1, %2};" : "=l"(r) : "f"(x), "f"(y)); return r;
}
__device__ __forceinline__ void upk(ull v, float& x, float& y) {
    asm("mov.b64 {%0, %1}, %2;" : "=f"(x), "=f"(y) : "l"(v));
}
__device__ __forceinline__ ull fma2(ull a, ull b, ull c) {
    ull d; asm("fma.rn.f32x2 %0, %1, %2, %3;" : "=l"(d) : "l"(a), "l"(b), "l"(c)); return d;
}
__device__ __forceinline__ ull add2(ull a, ull b) {
    ull d; asm("add.rn.f32x2 %0, %1, %2;" : "=l"(d) : "l"(a), "l"(b)); return d;
}

// ------- launch 1: embedding GEMM (blocks 0..781) + edge histogram (blocks 782+) -------
__global__ void emb_hist(const float* __restrict__ A, const float* __restrict__ W,
                         const float* __restrict__ bias, const int* __restrict__ ei) {
    int t = threadIdx.x;
    if (blockIdx.x >= 782) {
        int e = (blockIdx.x - 782) * 256 + t;
        if (e < E_EDGES) atomicAdd(&g_hist[ei[E_EDGES + e]], 1);
        return;
    }
    __shared__ float Ws[64][68];
    __shared__ float As[64][68];
    int row0 = blockIdx.x * 64;

    #pragma unroll
    for (int i = t; i < 4096; i += 256) { int c = i >> 6, k = i & 63; Ws[c][k] = W[i]; }
    #pragma unroll
    for (int i = t; i < 4096; i += 256) {
        int r = i >> 6, k = i & 63; int gr = row0 + r;
        As[r][k] = (gr < N_NODES) ? A[gr * 64 + k] : 0.f;
    }
    __syncthreads();

    int c  = t & 63;
    int rb = t >> 6;
    float acc[16];
    #pragma unroll
    for (int r = 0; r < 16; r++) acc[r] = 0.f;

    #pragma unroll
    for (int k4 = 0; k4 < 16; k4++) {
        float4 w4 = *(const float4*)&Ws[c][k4 * 4];
        #pragma unroll
        for (int r = 0; r < 16; r++) {
            float4 a4 = *(const float4*)&As[rb * 16 + r][k4 * 4];
            acc[r] += w4.x * a4.x + w4.y * a4.y + w4.z * a4.z + w4.w * a4.w;
        }
    }
    float bb = bias[c];
    #pragma unroll
    for (int r = 0; r < 16; r++) {
        int gr = row0 + rb * 16 + r;
        if (gr < N_NODES) g_h[gr * 64 + c] = acc[r] + bb;
    }
}

// ------- launch 2: block 0 scans hist -> offsets (and re-zeroes hist); others scatter ----
#define SCAT_BLOCKS 782           // ceil(800000/1024)
__global__ void scan_scatter(const int* __restrict__ ei, const float* __restrict__ eattr) {
    int t = threadIdx.x;           // 1024 threads
    if (blockIdx.x == 0) {
        __shared__ int sp[1024];
        const int CH = 49;         // 1024*49 = 50176 >= 50000
        int base = t * CH;
        int sum = 0;
        for (int i = 0; i < CH; i++) {
            int idx = base + i;
            if (idx < N_NODES) sum += g_hist[idx];
        }
        sp[t] = sum;
        __syncthreads();
        for (int off = 1; off < 1024; off <<= 1) {
            int v = (t >= off) ? sp[t - off] : 0;
            __syncthreads();
            sp[t] += v;
            __syncthreads();
        }
        int run = (t == 0) ? 0 : sp[t - 1];
        for (int i = 0; i < CH; i++) {
            int idx = base + i;
            if (idx < N_NODES) {
                g_off[idx] = run;
                g_cursor[idx] = run;
                run += g_hist[idx];
                g_hist[idx] = 0;          // reset for next graph replay
            }
        }
        if (t == 1023) g_off[N_NODES] = sp[1023];
        __threadfence();
        __syncthreads();
        if (t == 0) atomicExch(&g_flag, 1);
        return;
    }

    // scatter blocks: wait for offsets
    if (t == 0) { while (atomicAdd(&g_flag, 0) == 0) {} }
    __syncthreads();
    __threadfence();

    int e = (blockIdx.x - 1) * 1024 + t;
    if (e < E_EDGES) {
        int src = ei[e];
        int dst = ei[E_EDGES + e];
        int pos = atomicAdd(&g_cursor[dst], 1);
        g_srcS[pos] = src;
        const float4* s4 = (const float4*)(eattr + (size_t)e * 16);
        float4* d4 = (float4*)(g_eaS + (size_t)pos * 16);
        d4[0] = s4[0]; d4[1] = s4[1]; d4[2] = s4[2]; d4[3] = s4[3];
    }
    __syncthreads();
    if (t == 0) {
        int d = atomicAdd(&g_done, 1);
        if (d == SCAT_BLOCKS - 1) {        // last scatter block resets flags
            g_done = 0;
            atomicExch(&g_flag, 0);
        }
    }
}

// ---------------- fused xl/xr GEMM: one 128-output-column tile (lin_pool style) -----
__global__ void gemm_xlxr(const float* __restrict__ Wl, const float* __restrict__ bl,
                          const float* __restrict__ Wr, const float* __restrict__ br) {
    __shared__ float Ws[128][68];   // rows 0..63 = Wl, 64..127 = Wr
    __shared__ float As[32][68];
    int t = threadIdx.x;            // 256
    int row0 = blockIdx.x * 32;

    #pragma unroll
    for (int i = t; i < 4096; i += 256) {
        int c = i >> 6, k = i & 63;
        Ws[c][k]      = Wl[i];
        Ws[64 + c][k] = Wr[i];
    }
    #pragma unroll
    for (int i = t; i < 2048; i += 256) {
        int r = i >> 6, k = i & 63; int gr = row0 + r;
        As[r][k] = (gr < N_NODES) ? g_h[gr * 64 + k] : 0.f;
    }
    __syncthreads();

    int c  = t & 127;
    int rb = t >> 7;                // 0..1, 16 rows each
    float acc[16];
    #pragma unroll
    for (int r = 0; r < 16; r++) acc[r] = 0.f;

    #pragma unroll
    for (int k4 = 0; k4 < 16; k4++) {
        float4 w4 = *(const float4*)&Ws[c][k4 * 4];
        #pragma unroll
        for (int r = 0; r < 16; r++) {
            float4 a4 = *(const float4*)&As[rb * 16 + r][k4 * 4];
            acc[r] += w4.x * a4.x + w4.y * a4.y + w4.z * a4.z + w4.w * a4.w;
        }
    }
    float bb = (c < 64) ? bl[c] : br[c - 64];
    #pragma unroll
    for (int r = 0; r < 16; r++) {
        int gr = row0 + rb * 16 + r;
        if (gr < N_NODES) {
            if (c < 64) g_xl[gr * 64 + c]        = acc[r] + bb;
            else        g_xr[gr * 64 + (c - 64)] = acc[r] + bb;
        }
    }
}

// ---- fused GAT layer: warp/node, half-warp handles 2 edges per iteration (4/iter) ----
__global__ void __launch_bounds__(256, 3)
gat_layer(const float* __restrict__ We, const float* __restrict__ att,
          const float* __restrict__ cb, const float* __restrict__ gamma,
          const float* __restrict__ beta, const float* __restrict__ mean,
          const float* __restrict__ var) {
    __shared__ float4 sWe[16][16];   // sWe[k][cg] = We rows cg*4..cg*4+3 at col k
    int t = threadIdx.x;             // 256 threads = 8 warps = 8 nodes
    {
        int k = t >> 4, cg = t & 15;
        sWe[k][cg] = make_float4(We[(cg * 4 + 0) * 16 + k], We[(cg * 4 + 1) * 16 + k],
                                 We[(cg * 4 + 2) * 16 + k], We[(cg * 4 + 3) * 16 + k]);
    }
    __syncthreads();

    int nid = (blockIdx.x * 256 + t) >> 5;   // grid exact: 6250*8 = 50000
    int lane = t & 31;
    int half = lane >> 4;            // 0 or 1
    int cg   = lane & 15;            // channel group: channels cg*4 .. cg*4+3

    float4 vr = *(const float4*)&g_xr[nid * 64 + cg * 4];
    ull vr01 = pk(vr.x, vr.y), vr23 = pk(vr.z, vr.w);
    float4 a4 = __ldg((const float4*)att + cg);

    int jb = g_off[nid], je = g_off[nid + 1];

    ull acc01 = 0ull, acc23 = 0ull;
    float accd = 0.f;

    for (int j0 = jb; j0 < je; j0 += 4) {
        // half 0 -> edges j0, j0+1 ; half 1 -> edges j0+2, j0+3
        int jA = j0 + half * 2;
        int jB = jA + 1;
        bool vA = (jA < je), vB = (jB < je);
        int jAc = vA ? jA : jb;
        int jBc = vB ? jB : jb;

        int sA = __ldg(&g_srcS[jAc]);
        int sB = __ldg(&g_srcS[jBc]);
        float4 vlA = *(const float4*)&g_xl[sA * 64 + cg * 4];
        float4 vlB = *(const float4*)&g_xl[sB * 64 + cg * 4];
        ull vlA01 = pk(vlA.x, vlA.y), vlA23 = pk(vlA.z, vlA.w);
        ull vlB01 = pk(vlB.x, vlB.y), vlB23 = pk(vlB.z, vlB.w);

        ull mA01 = add2(vlA01, vr01), mA23 = add2(vlA23, vr23);
        ull mB01 = add2(vlB01, vr01), mB23 = add2(vlB23, vr23);

        const float4* eaA = (const float4*)(g_eaS + (size_t)jAc * 16);
        const float4* eaB = (const float4*)(g_eaS + (size_t)jBc * 16);

        #pragma unroll
        for (int q = 0; q < 4; q++) {
            float4 cA = eaA[q];
            float4 cB = eaB[q];
            #pragma unroll
            for (int kk = 0; kk < 4; kk++) {
                int k = q * 4 + kk;
                const ull* wp = (const ull*)&sWe[k][cg];
                ull w0 = wp[0], w1 = wp[1];
                float fA = (kk == 0) ? cA.x : (kk == 1) ? cA.y : (kk == 2) ? cA.z : cA.w;
                float fB = (kk == 0) ? cB.x : (kk == 1) ? cB.y : (kk == 2) ? cB.z : cB.w;
                ull aA = pk(fA, fA), aB = pk(fB, fB);
                mA01 = fma2(w0, aA, mA01); mA23 = fma2(w1, aA, mA23);
                mB01 = fma2(w0, aB, mB01); mB23 = fma2(w1, aB, mB23);
            }
        }

        float a0, a1, a2, a3, b0, b1, b2, b3;
        upk(mA01, a0, a1); upk(mA23, a2, a3);
        upk(mB01, b0, b1); upk(mB23, b2, b3);
        a0 = fmaxf(a0, NEG_SLOPE * a0); a1 = fmaxf(a1, NEG_SLOPE * a1);
        a2 = fmaxf(a2, NEG_SLOPE * a2); a3 = fmaxf(a3, NEG_SLOPE * a3);
        b0 = fmaxf(b0, NEG_SLOPE * b0); b1 = fmaxf(b1, NEG_SLOPE * b1);
        b2 = fmaxf(b2, NEG_SLOPE * b2); b3 = fmaxf(b3, NEG_SLOPE * b3);

        float pA = a0 * a4.x + a1 * a4.y + a2 * a4.z + a3 * a4.w;
        float pB = b0 * a4.x + b1 * a4.y + b2 * a4.z + b3 * a4.w;
        #pragma unroll
        for (int o = 1; o <= 8; o <<= 1) {
            pA += __shfl_xor_sync(0xffffffffu, pA, o);
            pB += __shfl_xor_sync(0xffffffffu, pB, o);
        }

        float wA = vA ? __expf(pA) : 0.f;   // logits small; stable without segment-max
        float wB = vB ? __expf(pB) : 0.f;
        accd += wA + wB;
        ull wwA = pk(wA, wA), wwB = pk(wB, wB);
        acc01 = fma2(wwA, vlA01, acc01); acc23 = fma2(wwA, vlA23, acc23);
        acc01 = fma2(wwB, vlB01, acc01); acc23 = fma2(wwB, vlB23, acc23);
    }

    float ax, ay, az, aw;
    upk(acc01, ax, ay); upk(acc23, az, aw);

    // merge the two half-warp accumulators
    ax += __shfl_xor_sync(0xffffffffu, ax, 16);
    ay += __shfl_xor_sync(0xffffffffu, ay, 16);
    az += __shfl_xor_sync(0xffffffffu, az, 16);
    aw += __shfl_xor_sync(0xffffffffu, aw, 16);
    accd += __shfl_xor_sync(0xffffffffu, accd, 16);

    if (half == 0) {
        float inv = 1.f / (accd + 1e-16f);
        float4 b4  = __ldg((const float4*)cb + cg);
        float4 mu4 = __ldg((const float4*)mean + cg);
        float4 v4  = __ldg((const float4*)var + cg);
        float4 gm4 = __ldg((const float4*)gamma + cg);
        float4 bt4 = __ldg((const float4*)beta + cg);
        float o[4] = {ax * inv + b4.x, ay * inv + b4.y,
                      az * inv + b4.z, aw * inv + b4.w};
        float mu[4] = {mu4.x, mu4.y, mu4.z, mu4.w};
        float vv[4] = {v4.x, v4.y, v4.z, v4.w};
        float gm[4] = {gm4.x, gm4.y, gm4.z, gm4.w};
        float bt[4] = {bt4.x, bt4.y, bt4.z, bt4.w};
        #pragma unroll
        for (int q = 0; q < 4; q++) {
            float z = (o[q] - mu[q]) * rsqrtf(vv[q] + BN_EPS) * gm[q] + bt[q];
            o[q] = 0.5f * z * (1.f + erff(z * 0.70710678118654752f));
        }
        float4 h = *(float4*)&g_h[nid * 64 + cg * 4];
        h.x += o[0]; h.y += o[1]; h.z += o[2]; h.w += o[3];
        *(float4*)&g_h[nid * 64 + cg * 4] = h;
    }
}

// ---------------- pooling ----------------
__global__ void init_pool(float* __restrict__ out) {
    int idx = blockIdx.x * blockDim.x + threadIdx.x;
    if (idx < G_GRAPHS * DOUT) out[idx] = 0.f;
    if (idx < G_GRAPHS) g_cnt[idx] = 0.f;
}

// lin projection fused with pooled sum AND node counting
__global__ void lin_pool(const float* __restrict__ W, const float* __restrict__ bias,
                         const int* __restrict__ batch, float* __restrict__ pooled) {
    __shared__ float Ws[128][68];
    __shared__ float As[32][68];
    int t = threadIdx.x;            // 256
    int row0 = blockIdx.x * 32;

    for (int i = t; i < 128 * 64; i += 256) { int c = i >> 6, k = i & 63; Ws[c][k] = W[i]; }
    for (int i = t; i < 32 * 64; i += 256) {
        int r = i >> 6, k = i & 63; int gr = row0 + r;
        As[r][k] = (gr < N_NODES) ? g_h[gr * 64 + k] : 0.f;
    }
    __syncthreads();

    int c  = t & 127;
    int rb = t >> 7;
    float acc[16];
    #pragma unroll
    for (int r = 0; r < 16; r++) acc[r] = 0.f;

    #pragma unroll
    for (int k4 = 0; k4 < 16; k4++) {
        float4 w4 = *(const float4*)&Ws[c][k4 * 4];
        #pragma unroll
        for (int r = 0; r < 16; r++) {
            float4 a4 = *(const float4*)&As[rb * 16 + r][k4 * 4];
            acc[r] += w4.x * a4.x + w4.y * a4.y + w4.z * a4.z + w4.w * a4.w;
        }
    }
    float bb = bias[c];
    #pragma unroll
    for (int r = 0; r < 16; r++) {
        int gr = row0 + rb * 16 + r;
        if (gr < N_NODES) {
            atomicAdd(&pooled[batch[gr] * DOUT + c], acc[r] + bb);
            if (c == 0) atomicAdd(&g_cnt[batch[gr]], 1.f);
        }
    }
}

__global__ void finalize(float* __restrict__ out) {
    int idx = blockIdx.x * blockDim.x + threadIdx.x;
    if (idx >= G_GRAPHS * DOUT) return;
    out[idx] /= fmaxf(g_cnt[idx >> 7], 1.f);
}

// ---------------- launch ----------------
extern "C" void kernel_launch(void* const* d_in, const int* in_sizes, int n_in,
                              void* d_out, int out_size) {
    const float* x         = (const float*)d_in[0];
    const int*   ei        = (const int*)  d_in[1];
    const float* eattr     = (const float*)d_in[2];
    const int*   batch     = (const int*)  d_in[3];
    const float* emb_W     = (const float*)d_in[4];
    const float* emb_b     = (const float*)d_in[5];
    const float* Wl        = (const float*)d_in[6];
    const float* bl        = (const float*)d_in[7];
    const float* Wr        = (const float*)d_in[8];
    const float* br        = (const float*)d_in[9];
    const float* We        = (const float*)d_in[10];
    const float* att       = (const float*)d_in[11];
    const float* conv_bias = (const float*)d_in[12];
    const float* gamma     = (const float*)d_in[13];
    const float* beta      = (const float*)d_in[14];
    const float* mean      = (const float*)d_in[15];
    const float* var       = (const float*)d_in[16];
    const float* lin_W     = (const float*)d_in[17];
    const float* lin_b     = (const float*)d_in[18];
    float* out = (float*)d_out;

    const int XLR_BLOCKS  = (N_NODES + 31) / 32;            // 1563
    const int GAT_BLOCKS  = N_NODES / 8;                    // 6250 (8 nodes/block, exact)

    emb_hist<<<782 + 3125, 256>>>(x, emb_W, emb_b, ei);
    scan_scatter<<<1 + SCAT_BLOCKS, 1024>>>(ei, eattr);

    for (int l = 0; l < LAYERS; l++) {
        gemm_xlxr<<<XLR_BLOCKS, 256>>>(Wl + l * 4096, bl + l * 64, Wr + l * 4096, br + l * 64);
        gat_layer<<<GAT_BLOCKS, 256>>>(We + l * 1024, att + l * 64, conv_bias + l * 64,
                                       gamma + l * 64, beta + l * 64, mean + l * 64, var + l * 64);
    }

    init_pool<<<(G_GRAPHS * DOUT + 255) / 256, 256>>>(out);
    lin_pool<<<(N_NODES + 31) / 32, 256>>>(lin_W, lin_b, batch, out);
    finalize<<<(G_GRAPHS * DOUT + 255) / 256, 256>>>(out);
}